// round 2
// baseline (speedup 1.0000x reference)
#include <cuda_runtime.h>
#include <cuda_bf16.h>

// Shapes (fixed by the problem)
#define B  4
#define Qn 256
#define Kn 1024
#define Dd 512
#define Hh 128
#define DV 512

// Scratch for projected q and k (no allocs allowed -> device globals)
__device__ float g_qh[B * Qn * Hh];   // 512 KB
__device__ float g_kh[B * Kn * Hh];   // 2 MB

// ---------------------------------------------------------------------------
// fast math helpers (approx MUFU ops; ex2/rcp approx have ~2^-22 rel error)
// ---------------------------------------------------------------------------
__device__ __forceinline__ float ex2a(float x) {
    float r; asm("ex2.approx.f32 %0, %1;" : "=f"(r) : "f"(x)); return r;
}
__device__ __forceinline__ float rcpa(float x) {
    float r; asm("rcp.approx.f32 %0, %1;" : "=f"(r) : "f"(x)); return r;
}
// accurate-enough tanh: tanh(x) = (e^{2x}-1)/(e^{2x}+1), clamped
__device__ __forceinline__ float tanh_fast(float x) {
    x = fminf(fmaxf(x, -15.0f), 15.0f);
    float e = ex2a(x * 2.885390081777926f);   // 2*log2(e)
    return (e - 1.0f) * rcpa(e + 1.0f);
}

// ---------------------------------------------------------------------------
// Projection GEMM: Out[m][h] = sum_d X[m][d] * W[h][d]
// Tile: 64 rows x 128 H (full H), D-tile 32. 256 threads, 4x8 micro-tile.
// which == 0 -> g_qh, which == 1 -> g_kh
// ---------------------------------------------------------------------------
__global__ void proj_kernel(const float* __restrict__ X,
                            const float* __restrict__ W,
                            int which) {
    float* Out = which ? g_kh : g_qh;
    __shared__ float Xs[32][65];
    __shared__ float Ws[32][129];

    const int row0 = blockIdx.x * 64;
    const int tid  = threadIdx.x;
    const int tx   = tid & 15;
    const int ty   = tid >> 4;

    float acc[4][8];
#pragma unroll
    for (int i = 0; i < 4; i++)
#pragma unroll
        for (int j = 0; j < 8; j++) acc[i][j] = 0.0f;

    for (int d0 = 0; d0 < Dd; d0 += 32) {
        // load X tile 64x32 (transposed into smem)
#pragma unroll
        for (int l = 0; l < 8; l++) {
            int e  = tid + 256 * l;
            int r  = e >> 5, dd = e & 31;
            Xs[dd][r] = X[(size_t)(row0 + r) * Dd + d0 + dd];
        }
        // load W tile 128x32 (transposed into smem)
#pragma unroll
        for (int l = 0; l < 16; l++) {
            int e  = tid + 256 * l;
            int h  = e >> 5, dd = e & 31;
            Ws[dd][h] = W[(size_t)h * Dd + d0 + dd];
        }
        __syncthreads();
#pragma unroll
        for (int dd = 0; dd < 32; dd++) {
            float xv[4], wv[8];
#pragma unroll
            for (int i = 0; i < 4; i++) xv[i] = Xs[dd][ty + 16 * i];
#pragma unroll
            for (int j = 0; j < 8; j++) wv[j] = Ws[dd][tx + 16 * j];
#pragma unroll
            for (int i = 0; i < 4; i++)
#pragma unroll
                for (int j = 0; j < 8; j++) acc[i][j] += xv[i] * wv[j];
        }
        __syncthreads();
    }
#pragma unroll
    for (int i = 0; i < 4; i++)
#pragma unroll
        for (int j = 0; j < 8; j++)
            Out[(size_t)(row0 + ty + 16 * i) * Hh + tx + 16 * j] = acc[i][j];
}

// ---------------------------------------------------------------------------
// Fused scores + softmax + A@V.
// Grid: B * (Q/4) = 256 CTAs, 128 threads (4 warps). Warp w owns q = q0 + w.
// Masked k-tiles (k >= valid_len) are skipped entirely: exp(-1e6 - m)
// underflows to exactly 0.0f, so skipping matches the reference bit-for-bit.
// ---------------------------------------------------------------------------
__global__ void attn_kernel(const float* __restrict__ v,
                            const int* __restrict__ vlens,
                            const float* __restrict__ w_v,
                            float* __restrict__ out) {
    __shared__ float qh_s[4][Hh];                 // 2 KB
    __shared__ float wv_s[Hh];                    // 0.5 KB
    __shared__ __align__(16) float buf[128 * 33]; // khT (h*33+k) / V tile (kk*512+d)
    __shared__ float p_s[4][Kn];                  // 16 KB (unnormalized probs)

    const int b    = blockIdx.x >> 6;
    const int q0   = (blockIdx.x & 63) * 4;
    const int tid  = threadIdx.x;
    const int lane = tid & 31;
    const int w    = tid >> 5;
    const int vl   = vlens[b];                    // int32 (JAX x64 disabled)

    // load qh rows (4x128) and w_v
    for (int i = tid; i < 4 * Hh; i += 128)
        qh_s[i >> 7][i & 127] = g_qh[(size_t)(b * Qn + q0 + (i >> 7)) * Hh + (i & 127)];
    if (tid < Hh) wv_s[tid] = w_v[tid];
    __syncthreads();

    // -------- Phase 1: scores. lane owns k = kt*32 + lane ------------------
    float s[32];
    const float* khb = g_kh + (size_t)b * Kn * Hh;

    for (int kt = 0; kt < 32; kt++) {
        const int k0 = kt * 32;
        if (k0 >= vl) { s[kt] = -1e6f; continue; }   // uniform across CTA
        // cooperative transpose-load of kh tile [32k x 128h] -> buf[h*33+k]
#pragma unroll
        for (int l = 0; l < 32; l++) {
            int e  = tid + 128 * l;
            int kl = e >> 7, h = e & 127;
            buf[h * 33 + kl] = khb[(size_t)(k0 + kl) * Hh + h];
        }
        __syncthreads();

        float a0 = 0.f, a1 = 0.f, a2 = 0.f, a3 = 0.f;
#pragma unroll
        for (int h = 0; h < Hh; h += 4) {
            a0 += wv_s[h + 0] * tanh_fast(qh_s[w][h + 0] + buf[(h + 0) * 33 + lane]);
            a1 += wv_s[h + 1] * tanh_fast(qh_s[w][h + 1] + buf[(h + 1) * 33 + lane]);
            a2 += wv_s[h + 2] * tanh_fast(qh_s[w][h + 2] + buf[(h + 2) * 33 + lane]);
            a3 += wv_s[h + 3] * tanh_fast(qh_s[w][h + 3] + buf[(h + 3) * 33 + lane]);
        }
        float acc = (a0 + a1) + (a2 + a3);
        s[kt] = (k0 + lane < vl) ? acc : -1e6f;
        __syncthreads();
    }

    // -------- Phase 2: softmax (per warp, in registers) --------------------
    float m = -3.4e38f;
#pragma unroll
    for (int kt = 0; kt < 32; kt++) m = fmaxf(m, s[kt]);
#pragma unroll
    for (int o = 16; o > 0; o >>= 1) m = fmaxf(m, __shfl_xor_sync(0xffffffffu, m, o));

    float Z = 0.f;
#pragma unroll
    for (int kt = 0; kt < 32; kt++) {
        float e = ex2a((s[kt] - m) * 1.4426950408889634f);
        Z += e;
        p_s[w][kt * 32 + lane] = e;
    }
#pragma unroll
    for (int o = 16; o > 0; o >>= 1) Z += __shfl_xor_sync(0xffffffffu, Z, o);
    const float invZ = 1.0f / Z;

    // -------- Phase 3: out = (P @ V) * invZ, V tiled 8k x 512d in smem -----
    float4 acc4[4];
#pragma unroll
    for (int j = 0; j < 4; j++) acc4[j] = make_float4(0.f, 0.f, 0.f, 0.f);

    const float* vb = v + (size_t)b * Kn * DV;
    for (int k0 = 0; k0 < Kn; k0 += 8) {
        if (k0 >= vl) break;                        // uniform; tails have p==0
        __syncthreads();                            // prev buf fully consumed
#pragma unroll
        for (int l = 0; l < 32; l++) {
            int e  = tid + 128 * l;
            int kl = e >> 9, d = e & 511;
            buf[kl * 512 + d] = vb[(size_t)(k0 + kl) * DV + d];
        }
        __syncthreads();
#pragma unroll
        for (int kk = 0; kk < 8; kk++) {
            float p = p_s[w][k0 + kk];
            const float4* vr = (const float4*)&buf[kk * 512];
#pragma unroll
            for (int j = 0; j < 4; j++) {
                float4 vv = vr[lane + 32 * j];
                acc4[j].x += p * vv.x;
                acc4[j].y += p * vv.y;
                acc4[j].z += p * vv.z;
                acc4[j].w += p * vv.w;
            }
        }
    }

    float* ob = out + (size_t)(b * Qn + q0 + w) * DV;
#pragma unroll
    for (int j = 0; j < 4; j++) {
        float4 o = acc4[j];
        o.x *= invZ; o.y *= invZ; o.z *= invZ; o.w *= invZ;
        ((float4*)ob)[lane + 32 * j] = o;
    }
}

// ---------------------------------------------------------------------------
extern "C" void kernel_launch(void* const* d_in, const int* in_sizes, int n_in,
                              void* d_out, int out_size) {
    const float* q    = (const float*)d_in[0];
    const float* k    = (const float*)d_in[1];
    const float* v    = (const float*)d_in[2];
    const int*   vlen = (const int*)d_in[3];
    const float* w_q  = (const float*)d_in[4];
    const float* w_k  = (const float*)d_in[5];
    const float* w_v  = (const float*)d_in[6];
    float*       out  = (float*)d_out;

    proj_kernel<<<(B * Qn) / 64, 256>>>(q, w_q, 0);   // qh: 1024 rows
    proj_kernel<<<(B * Kn) / 64, 256>>>(k, w_k, 1);   // kh: 4096 rows
    attn_kernel<<<B * (Qn / 4), 128>>>(v, vlen, w_v, out);
}

// round 3
// speedup vs baseline: 2.6565x; 2.6565x over previous
#include <cuda_runtime.h>

#define B  4
#define Qn 256
#define Kn 1024
#define Dd 512
#define Hh 128
#define DV 512

__device__ float g_qh[B * Qn * Hh];   // 512 KB
__device__ float g_kh[B * Kn * Hh];   // 2 MB

__device__ __forceinline__ float ex2a(float x) {
    float r; asm("ex2.approx.f32 %0, %1;" : "=f"(r) : "f"(x)); return r;
}
__device__ __forceinline__ float tanha(float x) {
    float r; asm("tanh.approx.f32 %0, %1;" : "=f"(r) : "f"(x)); return r;
}

// ---------------------------------------------------------------------------
// Merged projection GEMM: qh = q @ WqT (1024x128), kh = k @ WkT (4096x128).
// Tile 32 rows x 64 H, D-tile 32, 256 threads, micro 2x4, reg-staged prefetch.
// Grid: 64 (qh) + 256 (kh) = 320 CTAs.
// ---------------------------------------------------------------------------
__global__ void proj_kernel(const float* __restrict__ Xq, const float* __restrict__ Wq,
                            const float* __restrict__ Xk, const float* __restrict__ Wk) {
    __shared__ float Xs[32 * 34];   // [dd][row], pad 34
    __shared__ float Ws[32 * 68];   // [dd][h],   pad 68

    int bid = blockIdx.x;
    const float* X; const float* W; float* Out; int rt, ht;
    if (bid < 64) { X = Xq; W = Wq; Out = g_qh; rt = bid >> 1; ht = bid & 1; }
    else { bid -= 64; X = Xk; W = Wk; Out = g_kh; rt = bid >> 1; ht = bid & 1; }
    const int row0 = rt * 32, h0 = ht * 64;

    const int tid = threadIdx.x;
    const int tx  = tid & 15;       // 16 * 4 = 64 H cols
    const int ty  = tid >> 4;       // 16 * 2 = 32 rows
    const int xr  = tid >> 3;       // 0..31 (X row / W h-row)
    const int d4  = tid & 7;        // d-group of 4

    // prefetch D-tile 0
    float4 xp  = *(const float4*)&X[(size_t)(row0 + xr) * Dd + d4 * 4];
    float4 wp0 = *(const float4*)&W[(size_t)(h0 + xr) * Dd + d4 * 4];
    float4 wp1 = *(const float4*)&W[(size_t)(h0 + xr + 32) * Dd + d4 * 4];

    float acc[2][4];
#pragma unroll
    for (int r = 0; r < 2; r++)
#pragma unroll
        for (int c = 0; c < 4; c++) acc[r][c] = 0.0f;

    for (int t = 0; t < 16; t++) {
        __syncthreads();
        {
            int d = d4 * 4;
            Xs[(d + 0) * 34 + xr] = xp.x; Xs[(d + 1) * 34 + xr] = xp.y;
            Xs[(d + 2) * 34 + xr] = xp.z; Xs[(d + 3) * 34 + xr] = xp.w;
            Ws[(d + 0) * 68 + xr] = wp0.x; Ws[(d + 1) * 68 + xr] = wp0.y;
            Ws[(d + 2) * 68 + xr] = wp0.z; Ws[(d + 3) * 68 + xr] = wp0.w;
            Ws[(d + 0) * 68 + xr + 32] = wp1.x; Ws[(d + 1) * 68 + xr + 32] = wp1.y;
            Ws[(d + 2) * 68 + xr + 32] = wp1.z; Ws[(d + 3) * 68 + xr + 32] = wp1.w;
        }
        __syncthreads();
        if (t < 15) {
            int dn = (t + 1) * 32 + d4 * 4;
            xp  = *(const float4*)&X[(size_t)(row0 + xr) * Dd + dn];
            wp0 = *(const float4*)&W[(size_t)(h0 + xr) * Dd + dn];
            wp1 = *(const float4*)&W[(size_t)(h0 + xr + 32) * Dd + dn];
        }
#pragma unroll
        for (int dd = 0; dd < 32; dd++) {
            float2 xv = *(const float2*)&Xs[dd * 34 + ty * 2];
            float4 wv = *(const float4*)&Ws[dd * 68 + tx * 4];
            acc[0][0] += xv.x * wv.x; acc[0][1] += xv.x * wv.y;
            acc[0][2] += xv.x * wv.z; acc[0][3] += xv.x * wv.w;
            acc[1][0] += xv.y * wv.x; acc[1][1] += xv.y * wv.y;
            acc[1][2] += xv.y * wv.z; acc[1][3] += xv.y * wv.w;
        }
    }
#pragma unroll
    for (int r = 0; r < 2; r++) {
        float4 o = make_float4(acc[r][0], acc[r][1], acc[r][2], acc[r][3]);
        *(float4*)&Out[(size_t)(row0 + ty * 2 + r) * Hh + h0 + tx * 4] = o;
    }
}

// ---------------------------------------------------------------------------
// Fused scores + softmax + P@V. Grid B*(Q/8)=128 CTAs, 256 threads (8 warps).
// Phase 1: warp w owns q row w; lane owns k within 32-wide tiles; writes raw
//          scores to p_s[w][k].  Masked tiles skipped (exp underflows to 0).
// Phase 2: per-warp softmax; p_s rewritten as normalized probabilities.
// Phase 3: warp w -> q pair (w&3), DV half (w>>2); 2 FMA per V smem read.
// Dynamic smem 54.25 KB:  p_s[8*1024] | kh[32*132] (-> V[8*512]) | qh[8*128] | wv[128]
// ---------------------------------------------------------------------------
__global__ void attn_kernel(const float* __restrict__ v, const int* __restrict__ vlens,
                            const float* __restrict__ w_v, float* __restrict__ out) {
    extern __shared__ __align__(16) float sm[];
    float* p_s  = sm;            // 8192 floats
    float* kv_s = sm + 8192;     // 4224 floats (kh padded 132) / V tile 4096
    float* qh_s = sm + 12416;    // 1024
    float* wv_s = sm + 13440;    // 128

    const int b    = blockIdx.x >> 5;
    const int q0   = (blockIdx.x & 31) * 8;
    const int tid  = threadIdx.x;
    const int lane = tid & 31;
    const int w    = tid >> 5;
    const int vl   = vlens[b];

    // load qh rows (8x128, contiguous) + w_v
    ((float4*)qh_s)[tid] = ((const float4*)(g_qh + (size_t)(b * Qn + q0) * Hh))[tid];
    if (tid < Hh) wv_s[tid] = w_v[tid];

    // ---------------- Phase 1: scores -------------------------------------
    const float* khg  = g_kh + (size_t)b * Kn * Hh;
    const int ktmax = (vl + 31) >> 5;

    float4 kpre[4];
#pragma unroll
    for (int i = 0; i < 4; i++) {
        int e = tid + 256 * i;
        kpre[i] = *(const float4*)&khg[(size_t)(e >> 5) * Hh + (e & 31) * 4];
    }

    float* prow = p_s + w * Kn + lane;
    for (int t = 0; t < ktmax; t++) {
        __syncthreads();
#pragma unroll
        for (int i = 0; i < 4; i++) {
            int e = tid + 256 * i;
            *(float4*)&kv_s[(e >> 5) * 132 + (e & 31) * 4] = kpre[i];
        }
        __syncthreads();
        if (t + 1 < ktmax) {
            int k0n = (t + 1) * 32;
#pragma unroll
            for (int i = 0; i < 4; i++) {
                int e = tid + 256 * i;
                kpre[i] = *(const float4*)&khg[(size_t)(k0n + (e >> 5)) * Hh + (e & 31) * 4];
            }
        }
        const float4* kv4 = (const float4*)&kv_s[lane * 132];
        const float4* qv4 = (const float4*)&qh_s[w * Hh];
        const float4* wv4 = (const float4*)wv_s;
        float a0 = 0.f, a1 = 0.f, a2 = 0.f, a3 = 0.f;
#pragma unroll
        for (int hb = 0; hb < 32; hb++) {
            float4 kv = kv4[hb];
            float4 qv = qv4[hb];
            float4 wv = wv4[hb];
            a0 += wv.x * tanha(qv.x + kv.x);
            a1 += wv.y * tanha(qv.y + kv.y);
            a2 += wv.z * tanha(qv.z + kv.z);
            a3 += wv.w * tanha(qv.w + kv.w);
        }
        int k = t * 32 + lane;
        prow[t * 32] = (k < vl) ? ((a0 + a1) + (a2 + a3)) : -1e6f;
    }
    for (int t = ktmax; t < 32; t++) prow[t * 32] = -1e6f;

    // ---------------- Phase 2: softmax (warp-local) ------------------------
    float m = -3.4e38f;
#pragma unroll
    for (int t = 0; t < 32; t++) m = fmaxf(m, prow[t * 32]);
#pragma unroll
    for (int o = 16; o > 0; o >>= 1) m = fmaxf(m, __shfl_xor_sync(0xffffffffu, m, o));

    float e_[32];
    float Z = 0.f;
#pragma unroll
    for (int t = 0; t < 32; t++) {
        e_[t] = ex2a((prow[t * 32] - m) * 1.4426950408889634f);
        Z += e_[t];
    }
#pragma unroll
    for (int o = 16; o > 0; o >>= 1) Z += __shfl_xor_sync(0xffffffffu, Z, o);
    const float invZ = 1.0f / Z;
#pragma unroll
    for (int t = 0; t < 32; t++) prow[t * 32] = e_[t] * invZ;

    // ---------------- Phase 3: out = P @ V --------------------------------
    const int qp   = (w & 3) * 2;      // q pair
    const int doff = (w >> 2) * 64;    // DV half, in float4 units
    const float* vb = v + (size_t)b * Kn * DV;
    const int n3 = (vl + 7) >> 3;

    float4 vpre[4];
#pragma unroll
    for (int i = 0; i < 4; i++) {
        int e = tid + 256 * i;
        vpre[i] = *(const float4*)&vb[(size_t)(e >> 7) * DV + (e & 127) * 4];
    }

    float4 acc[2][2];
#pragma unroll
    for (int r = 0; r < 2; r++)
#pragma unroll
        for (int j = 0; j < 2; j++) acc[r][j] = make_float4(0.f, 0.f, 0.f, 0.f);

    const float* p0 = p_s + qp * Kn;
    const float* p1 = p_s + (qp + 1) * Kn;

    for (int t = 0; t < n3; t++) {
        __syncthreads();
#pragma unroll
        for (int i = 0; i < 4; i++) {
            int e = tid + 256 * i;
            *(float4*)&kv_s[(e >> 7) * DV + (e & 127) * 4] = vpre[i];
        }
        __syncthreads();
        if (t + 1 < n3) {
            int k0n = (t + 1) * 8;
#pragma unroll
            for (int i = 0; i < 4; i++) {
                int e = tid + 256 * i;
                vpre[i] = *(const float4*)&vb[(size_t)(k0n + (e >> 7)) * DV + (e & 127) * 4];
            }
        }
        int k0 = t * 8;
#pragma unroll
        for (int kk = 0; kk < 8; kk++) {
            float pa = p0[k0 + kk];
            float pb = p1[k0 + kk];
            const float4* vr = (const float4*)&kv_s[kk * DV];
#pragma unroll
            for (int j = 0; j < 2; j++) {
                float4 vv = vr[doff + lane + 32 * j];
                acc[0][j].x += pa * vv.x; acc[0][j].y += pa * vv.y;
                acc[0][j].z += pa * vv.z; acc[0][j].w += pa * vv.w;
                acc[1][j].x += pb * vv.x; acc[1][j].y += pb * vv.y;
                acc[1][j].z += pb * vv.z; acc[1][j].w += pb * vv.w;
            }
        }
    }

#pragma unroll
    for (int r = 0; r < 2; r++) {
        float* ob = out + (size_t)(b * Qn + q0 + qp + r) * DV;
#pragma unroll
        for (int j = 0; j < 2; j++)
            ((float4*)ob)[doff + lane + 32 * j] = acc[r][j];
    }
}

// ---------------------------------------------------------------------------
extern "C" void kernel_launch(void* const* d_in, const int* in_sizes, int n_in,
                              void* d_out, int out_size) {
    const float* q    = (const float*)d_in[0];
    const float* k    = (const float*)d_in[1];
    const float* v    = (const float*)d_in[2];
    const int*   vlen = (const int*)d_in[3];
    const float* w_q  = (const float*)d_in[4];
    const float* w_k  = (const float*)d_in[5];
    const float* w_v  = (const float*)d_in[6];
    float*       out  = (float*)d_out;

    const int smem = (8192 + 4224 + 1024 + 128) * 4;   // 54272 B
    cudaFuncSetAttribute(attn_kernel, cudaFuncAttributeMaxDynamicSharedMemorySize, smem);

    proj_kernel<<<320, 256>>>(q, w_q, k, w_k);
    attn_kernel<<<128, 256, smem>>>(v, vlen, w_v, out);
}

// round 5
// speedup vs baseline: 2.7123x; 1.0210x over previous
#include <cuda_runtime.h>

#define B  4
#define Qn 256
#define Kn 1024
#define Dd 512
#define Hh 128
#define DV 512

__device__ float g_qh[B * Qn * Hh];   // 512 KB
__device__ float g_kh[B * Kn * Hh];   // 2 MB
__device__ float g_s[B * Qn * Kn];    // 4 MB raw scores

__device__ __forceinline__ float ex2a(float x) {
    float r; asm("ex2.approx.f32 %0, %1;" : "=f"(r) : "f"(x)); return r;
}
__device__ __forceinline__ float tanha(float x) {
    float r; asm("tanh.approx.f32 %0, %1;" : "=f"(r) : "f"(x)); return r;
}

// ---------------------------------------------------------------------------
// Merged projection GEMM (measured at scalar-FFMA floor ~21us).
// ---------------------------------------------------------------------------
__global__ void proj_kernel(const float* __restrict__ Xq, const float* __restrict__ Wq,
                            const float* __restrict__ Xk, const float* __restrict__ Wk) {
    __shared__ float Xs[32 * 34];
    __shared__ float Ws[32 * 68];

    int bid = blockIdx.x;
    const float* X; const float* W; float* Out; int rt, ht;
    if (bid < 64) { X = Xq; W = Wq; Out = g_qh; rt = bid >> 1; ht = bid & 1; }
    else { bid -= 64; X = Xk; W = Wk; Out = g_kh; rt = bid >> 1; ht = bid & 1; }
    const int row0 = rt * 32, h0 = ht * 64;

    const int tid = threadIdx.x;
    const int tx  = tid & 15;
    const int ty  = tid >> 4;
    const int xr  = tid >> 3;
    const int d4  = tid & 7;

    float4 xp  = *(const float4*)&X[(size_t)(row0 + xr) * Dd + d4 * 4];
    float4 wp0 = *(const float4*)&W[(size_t)(h0 + xr) * Dd + d4 * 4];
    float4 wp1 = *(const float4*)&W[(size_t)(h0 + xr + 32) * Dd + d4 * 4];

    float acc[2][4];
#pragma unroll
    for (int r = 0; r < 2; r++)
#pragma unroll
        for (int c = 0; c < 4; c++) acc[r][c] = 0.0f;

    for (int t = 0; t < 16; t++) {
        __syncthreads();
        {
            int d = d4 * 4;
            Xs[(d + 0) * 34 + xr] = xp.x; Xs[(d + 1) * 34 + xr] = xp.y;
            Xs[(d + 2) * 34 + xr] = xp.z; Xs[(d + 3) * 34 + xr] = xp.w;
            Ws[(d + 0) * 68 + xr] = wp0.x; Ws[(d + 1) * 68 + xr] = wp0.y;
            Ws[(d + 2) * 68 + xr] = wp0.z; Ws[(d + 3) * 68 + xr] = wp0.w;
            Ws[(d + 0) * 68 + xr + 32] = wp1.x; Ws[(d + 1) * 68 + xr + 32] = wp1.y;
            Ws[(d + 2) * 68 + xr + 32] = wp1.z; Ws[(d + 3) * 68 + xr + 32] = wp1.w;
        }
        __syncthreads();
        if (t < 15) {
            int dn = (t + 1) * 32 + d4 * 4;
            xp  = *(const float4*)&X[(size_t)(row0 + xr) * Dd + dn];
            wp0 = *(const float4*)&W[(size_t)(h0 + xr) * Dd + dn];
            wp1 = *(const float4*)&W[(size_t)(h0 + xr + 32) * Dd + dn];
        }
#pragma unroll
        for (int dd = 0; dd < 32; dd++) {
            float2 xv = *(const float2*)&Xs[dd * 34 + ty * 2];
            float4 wv = *(const float4*)&Ws[dd * 68 + tx * 4];
            acc[0][0] += xv.x * wv.x; acc[0][1] += xv.x * wv.y;
            acc[0][2] += xv.x * wv.z; acc[0][3] += xv.x * wv.w;
            acc[1][0] += xv.y * wv.x; acc[1][1] += xv.y * wv.y;
            acc[1][2] += xv.y * wv.z; acc[1][3] += xv.y * wv.w;
        }
    }
#pragma unroll
    for (int r = 0; r < 2; r++) {
        float4 o = make_float4(acc[r][0], acc[r][1], acc[r][2], acc[r][3]);
        *(float4*)&Out[(size_t)(row0 + ty * 2 + r) * Hh + h0 + tx * 4] = o;
    }
}

// ---------------------------------------------------------------------------
// Scores kernel. Grid = B * (Q/16) * (K/64) = 1024 CTAs, 256 threads.
// ---------------------------------------------------------------------------
__global__ void score_kernel(const int* __restrict__ vlens,
                             const float* __restrict__ w_v) {
    __shared__ float kh_s[Hh * 65];
    __shared__ float qh_s[16 * Hh];
    __shared__ float wv_s[Hh];

    const int bx = blockIdx.x;
    const int b  = bx >> 8;
    const int qt = (bx >> 4) & 15;
    const int kt = bx & 15;
    const int q0 = qt * 16;
    const int k0 = kt * 64;

    if (k0 >= vlens[b]) return;         // fully masked tile: never read later

    const int tid  = threadIdx.x;
    const int lane = tid & 31;
    const int w    = tid >> 5;

    {
        const float4* src = (const float4*)(g_qh + (size_t)(b * Qn + q0) * Hh);
        ((float4*)qh_s)[tid]       = src[tid];
        ((float4*)qh_s)[tid + 256] = src[tid + 256];
    }
    if (tid < Hh) wv_s[tid] = w_v[tid];

    {
        const float* khg = g_kh + (size_t)(b * Kn + k0) * Hh;
#pragma unroll
        for (int i = 0; i < 8; i++) {
            int e  = tid + 256 * i;
            int kr = e >> 5;
            int h4 = (e & 31) * 4;
            float4 vv = *(const float4*)&khg[(size_t)kr * Hh + h4];
            kh_s[(h4 + 0) * 65 + kr] = vv.x;
            kh_s[(h4 + 1) * 65 + kr] = vv.y;
            kh_s[(h4 + 2) * 65 + kr] = vv.z;
            kh_s[(h4 + 3) * 65 + kr] = vv.w;
        }
    }
    __syncthreads();

    const float* q0p = qh_s + (2 * w) * Hh;
    const float* q1p = qh_s + (2 * w + 1) * Hh;

    float s00 = 0.f, s01 = 0.f, s10 = 0.f, s11 = 0.f;
#pragma unroll 4
    for (int h = 0; h < Hh; h++) {
        float ka = kh_s[h * 65 + lane];
        float kb = kh_s[h * 65 + lane + 32];
        float qa = q0p[h];
        float qb = q1p[h];
        float wvv = wv_s[h];
        s00 += wvv * tanha(qa + ka);
        s01 += wvv * tanha(qa + kb);
        s10 += wvv * tanha(qb + ka);
        s11 += wvv * tanha(qb + kb);
    }

    float* so = g_s + (size_t)(b * Qn + q0 + 2 * w) * Kn + k0;
    so[lane]           = s00;
    so[lane + 32]      = s01;
    so[Kn + lane]      = s10;
    so[Kn + lane + 32] = s11;
}

// ---------------------------------------------------------------------------
// Softmax + P@V. Grid = B * (Q/8) * 2 = 256 CTAs, 256 threads (8 warps).
// ---------------------------------------------------------------------------
__global__ void pv_kernel(const float* __restrict__ v, const int* __restrict__ vlens,
                          float* __restrict__ out) {
    extern __shared__ __align__(16) float sm[];
    float* p_s = sm;           // 8192 floats
    float* v_s = sm + 8192;    // 4096 floats (16 k-rows x 256 dv)

    const int bx  = blockIdx.x;
    const int b   = bx >> 6;
    const int qg  = (bx >> 1) & 31;
    const int dvs = bx & 1;
    const int q0  = qg * 8;
    const int dv0 = dvs * 256;

    const int tid  = threadIdx.x;
    const int lane = tid & 31;
    const int w    = tid >> 5;
    const int vl   = vlens[b];

    // ---- softmax, warp w owns row q0+w -----------------------------------
    {
        const float* srow = g_s + (size_t)(b * Qn + q0 + w) * Kn;
        float e_[32];
        float m = -3.4e38f;
#pragma unroll
        for (int t = 0; t < 32; t++) {
            int k = t * 32 + lane;
            e_[t] = (k < vl) ? srow[k] : -1e6f;
            m = fmaxf(m, e_[t]);
        }
#pragma unroll
        for (int o = 16; o > 0; o >>= 1) m = fmaxf(m, __shfl_xor_sync(0xffffffffu, m, o));
        float Z = 0.f;
#pragma unroll
        for (int t = 0; t < 32; t++) {
            e_[t] = ex2a((e_[t] - m) * 1.4426950408889634f);
            Z += e_[t];
        }
#pragma unroll
        for (int o = 16; o > 0; o >>= 1) Z += __shfl_xor_sync(0xffffffffu, Z, o);
        float invZ = 1.0f / Z;
#pragma unroll
        for (int t = 0; t < 32; t++) p_s[w * Kn + t * 32 + lane] = e_[t] * invZ;
    }
    __syncthreads();

    // ---- P @ V ------------------------------------------------------------
    const int qp = (w & 3) * 2;            // q pair within the 8-row group
    const int dq = (w >> 2) * 32;          // float4 offset into the 256-dv half
    const float* vb = v + (size_t)b * Kn * DV + dv0;
    const int n3 = (vl + 15) >> 4;

    // V tile: 16 k-rows x 256 dv = 1024 float4 -> 4 per thread
    float4 vpre[4];
#pragma unroll
    for (int i = 0; i < 4; i++) {
        int e = tid + 256 * i;
        vpre[i] = *(const float4*)&vb[(size_t)(e >> 6) * DV + (e & 63) * 4];
    }

    float4 acc0 = {0,0,0,0};
    float4 acc1 = {0,0,0,0};

    const float* p0 = p_s + qp * Kn;
    const float* p1 = p_s + (qp + 1) * Kn;

    for (int t = 0; t < n3; t++) {
        __syncthreads();
#pragma unroll
        for (int i = 0; i < 4; i++) {
            int e = tid + 256 * i;
            *(float4*)&v_s[(e >> 6) * 256 + (e & 63) * 4] = vpre[i];
        }
        __syncthreads();
        if (t + 1 < n3) {
            int kn = (t + 1) * 16;
#pragma unroll
            for (int i = 0; i < 4; i++) {
                int e = tid + 256 * i;
                vpre[i] = *(const float4*)&vb[(size_t)(kn + (e >> 6)) * DV + (e & 63) * 4];
            }
        }
        int k0 = t * 16;
#pragma unroll
        for (int k4 = 0; k4 < 4; k4++) {
            float4 pa = *(const float4*)&p0[k0 + k4 * 4];
            float4 pb = *(const float4*)&p1[k0 + k4 * 4];
            const float pav[4] = {pa.x, pa.y, pa.z, pa.w};
            const float pbv[4] = {pb.x, pb.y, pb.z, pb.w};
#pragma unroll
            for (int kk = 0; kk < 4; kk++) {
                float4 vv = ((const float4*)&v_s[(k4 * 4 + kk) * 256])[dq + lane];
                acc0.x += pav[kk] * vv.x; acc0.y += pav[kk] * vv.y;
                acc0.z += pav[kk] * vv.z; acc0.w += pav[kk] * vv.w;
                acc1.x += pbv[kk] * vv.x; acc1.y += pbv[kk] * vv.y;
                acc1.z += pbv[kk] * vv.z; acc1.w += pbv[kk] * vv.w;
            }
        }
    }

    {
        float* ob0 = out + (size_t)(b * Qn + q0 + qp) * DV + dv0;
        float* ob1 = out + (size_t)(b * Qn + q0 + qp + 1) * DV + dv0;
        ((float4*)ob0)[dq + lane] = acc0;
        ((float4*)ob1)[dq + lane] = acc1;
    }
}

// ---------------------------------------------------------------------------
extern "C" void kernel_launch(void* const* d_in, const int* in_sizes, int n_in,
                              void* d_out, int out_size) {
    const float* q    = (const float*)d_in[0];
    const float* k    = (const float*)d_in[1];
    const float* v    = (const float*)d_in[2];
    const int*   vlen = (const int*)d_in[3];
    const float* w_q  = (const float*)d_in[4];
    const float* w_k  = (const float*)d_in[5];
    const float* w_v  = (const float*)d_in[6];
    float*       out  = (float*)d_out;

    const int pv_smem = (8192 + 4096) * 4;   // 49152 B
    cudaFuncSetAttribute(pv_kernel, cudaFuncAttributeMaxDynamicSharedMemorySize, pv_smem);

    proj_kernel<<<320, 256>>>(q, w_q, k, w_k);
    score_kernel<<<1024, 256>>>(vlen, w_v);
    pv_kernel<<<256, 256, pv_smem>>>(v, vlen, out);
}

// round 6
// speedup vs baseline: 3.1522x; 1.1622x over previous
#include <cuda_runtime.h>

#define B  4
#define Qn 256
#define Kn 1024
#define Dd 512
#define Hh 128
#define DV 512

#define ROWS_ALL (B * Qn + B * Kn)          // 5120 projected rows total

__device__ float g_qh[B * Qn * Hh];         // 512 KB
__device__ float g_kh[B * Kn * Hh];         // 2 MB
__device__ float g_s[B * Qn * Kn];          // 4 MB raw scores
__device__ float g_pp[2][ROWS_ALL * Hh];    // 5 MB K-split partials

__device__ __forceinline__ float ex2a(float x) {
    float r; asm("ex2.approx.f32 %0, %1;" : "=f"(r) : "f"(x)); return r;
}
__device__ __forceinline__ float tanha(float x) {
    float r; asm("tanh.approx.f32 %0, %1;" : "=f"(r) : "f"(x)); return r;
}

// ---------------------------------------------------------------------------
// Projection GEMM v3: partial[ks][row][h] = sum_{d in chunk ks} X[row][d]W[h][d]
// Grid 640 = 160 row-tiles x 2 h-tiles x 2 k-splits; 128 threads; micro 4x4.
// Crossbar demand 2B/FMA with broadcast X reads -> FMA-pipe bound.
// ---------------------------------------------------------------------------
__global__ void proj_kernel(const float* __restrict__ Xq, const float* __restrict__ Wq,
                            const float* __restrict__ Xk, const float* __restrict__ Wk) {
    __shared__ float Xs[32 * 36];
    __shared__ float Ws[32 * 68];

    const int bid = blockIdx.x;
    const int rt  = bid >> 2;
    const int ht  = (bid >> 1) & 1;
    const int ks  = bid & 1;
    const int r0  = rt * 32;
    const int h0  = ht * 64;
    const int d0  = ks * 256;

    const float* Xbase = (r0 < B * Qn) ? (Xq + (size_t)r0 * Dd)
                                       : (Xk + (size_t)(r0 - B * Qn) * Dd);
    const float* W = (r0 < B * Qn) ? Wq : Wk;

    const int tid = threadIdx.x;
    const int tx  = tid & 15;       // 16 x 4 = 64 H
    const int ty  = tid >> 4;       // 8 x 4 = 32 rows

    float acc[4][4];
#pragma unroll
    for (int r = 0; r < 4; r++)
#pragma unroll
        for (int c = 0; c < 4; c++) acc[r][c] = 0.0f;

    for (int s = 0; s < 8; s++) {
        const int ds = d0 + s * 32;
        __syncthreads();
        // X tile 32r x 32d (transposed into Xs[d][r])
#pragma unroll
        for (int i = 0; i < 2; i++) {
            int e = tid + 128 * i;
            int r = e >> 3, c4 = (e & 7) * 4;
            float4 xv = *(const float4*)&Xbase[(size_t)r * Dd + ds + c4];
            Xs[(c4 + 0) * 36 + r] = xv.x;
            Xs[(c4 + 1) * 36 + r] = xv.y;
            Xs[(c4 + 2) * 36 + r] = xv.z;
            Xs[(c4 + 3) * 36 + r] = xv.w;
        }
        // W tile 64h x 32d (transposed into Ws[d][h])
#pragma unroll
        for (int i = 0; i < 4; i++) {
            int e = tid + 128 * i;
            int h = e >> 3, c4 = (e & 7) * 4;
            float4 wv = *(const float4*)&W[(size_t)(h0 + h) * Dd + ds + c4];
            Ws[(c4 + 0) * 68 + h] = wv.x;
            Ws[(c4 + 1) * 68 + h] = wv.y;
            Ws[(c4 + 2) * 68 + h] = wv.z;
            Ws[(c4 + 3) * 68 + h] = wv.w;
        }
        __syncthreads();
#pragma unroll
        for (int dd = 0; dd < 32; dd++) {
            float4 xv = *(const float4*)&Xs[dd * 36 + ty * 4];
            float4 wv = *(const float4*)&Ws[dd * 68 + tx * 4];
            acc[0][0] += xv.x * wv.x; acc[0][1] += xv.x * wv.y;
            acc[0][2] += xv.x * wv.z; acc[0][3] += xv.x * wv.w;
            acc[1][0] += xv.y * wv.x; acc[1][1] += xv.y * wv.y;
            acc[1][2] += xv.y * wv.z; acc[1][3] += xv.y * wv.w;
            acc[2][0] += xv.z * wv.x; acc[2][1] += xv.z * wv.y;
            acc[2][2] += xv.z * wv.z; acc[2][3] += xv.z * wv.w;
            acc[3][0] += xv.w * wv.x; acc[3][1] += xv.w * wv.y;
            acc[3][2] += xv.w * wv.z; acc[3][3] += xv.w * wv.w;
        }
    }

    float* pp = g_pp[ks];
#pragma unroll
    for (int r = 0; r < 4; r++) {
        float4 o = make_float4(acc[r][0], acc[r][1], acc[r][2], acc[r][3]);
        *(float4*)&pp[(size_t)(r0 + ty * 4 + r) * Hh + h0 + tx * 4] = o;
    }
}

// ---------------------------------------------------------------------------
// Reduce the two K-split partials into g_qh / g_kh. 640 x 256, 1 float4 each.
// ---------------------------------------------------------------------------
__global__ void proj_reduce_kernel() {
    const int i = blockIdx.x * 256 + threadIdx.x;           // float4 index
    const float4 a = ((const float4*)g_pp[0])[i];
    const float4 b = ((const float4*)g_pp[1])[i];
    float4 o = make_float4(a.x + b.x, a.y + b.y, a.z + b.z, a.w + b.w);
    const int qlim = (B * Qn * Hh) / 4;                     // 32768
    if (i < qlim) ((float4*)g_qh)[i] = o;
    else          ((float4*)g_kh)[i - qlim] = o;
}

// ---------------------------------------------------------------------------
// Scores kernel (unchanged). Grid = B*(Q/16)*(K/64) = 1024 CTAs, 256 threads.
// ---------------------------------------------------------------------------
__global__ void score_kernel(const int* __restrict__ vlens,
                             const float* __restrict__ w_v) {
    __shared__ float kh_s[Hh * 65];
    __shared__ float qh_s[16 * Hh];
    __shared__ float wv_s[Hh];

    const int bx = blockIdx.x;
    const int b  = bx >> 8;
    const int qt = (bx >> 4) & 15;
    const int kt = bx & 15;
    const int q0 = qt * 16;
    const int k0 = kt * 64;

    if (k0 >= vlens[b]) return;

    const int tid  = threadIdx.x;
    const int lane = tid & 31;
    const int w    = tid >> 5;

    {
        const float4* src = (const float4*)(g_qh + (size_t)(b * Qn + q0) * Hh);
        ((float4*)qh_s)[tid]       = src[tid];
        ((float4*)qh_s)[tid + 256] = src[tid + 256];
    }
    if (tid < Hh) wv_s[tid] = w_v[tid];

    {
        const float* khg = g_kh + (size_t)(b * Kn + k0) * Hh;
#pragma unroll
        for (int i = 0; i < 8; i++) {
            int e  = tid + 256 * i;
            int kr = e >> 5;
            int h4 = (e & 31) * 4;
            float4 vv = *(const float4*)&khg[(size_t)kr * Hh + h4];
            kh_s[(h4 + 0) * 65 + kr] = vv.x;
            kh_s[(h4 + 1) * 65 + kr] = vv.y;
            kh_s[(h4 + 2) * 65 + kr] = vv.z;
            kh_s[(h4 + 3) * 65 + kr] = vv.w;
        }
    }
    __syncthreads();

    const float* q0p = qh_s + (2 * w) * Hh;
    const float* q1p = qh_s + (2 * w + 1) * Hh;

    float s00 = 0.f, s01 = 0.f, s10 = 0.f, s11 = 0.f;
#pragma unroll 4
    for (int h = 0; h < Hh; h++) {
        float ka = kh_s[h * 65 + lane];
        float kb = kh_s[h * 65 + lane + 32];
        float qa = q0p[h];
        float qb = q1p[h];
        float wvv = wv_s[h];
        s00 += wvv * tanha(qa + ka);
        s01 += wvv * tanha(qa + kb);
        s10 += wvv * tanha(qb + ka);
        s11 += wvv * tanha(qb + kb);
    }

    float* so = g_s + (size_t)(b * Qn + q0 + 2 * w) * Kn + k0;
    so[lane]           = s00;
    so[lane + 32]      = s01;
    so[Kn + lane]      = s10;
    so[Kn + lane + 32] = s11;
}

// ---------------------------------------------------------------------------
// Softmax + P@V (unchanged). Grid = B*(Q/8)*2 = 256 CTAs, 256 threads.
// ---------------------------------------------------------------------------
__global__ void pv_kernel(const float* __restrict__ v, const int* __restrict__ vlens,
                          float* __restrict__ out) {
    extern __shared__ __align__(16) float sm[];
    float* p_s = sm;           // 8192 floats
    float* v_s = sm + 8192;    // 4096 floats (16 k-rows x 256 dv)

    const int bx  = blockIdx.x;
    const int b   = bx >> 6;
    const int qg  = (bx >> 1) & 31;
    const int dvs = bx & 1;
    const int q0  = qg * 8;
    const int dv0 = dvs * 256;

    const int tid  = threadIdx.x;
    const int lane = tid & 31;
    const int w    = tid >> 5;
    const int vl   = vlens[b];

    {
        const float* srow = g_s + (size_t)(b * Qn + q0 + w) * Kn;
        float e_[32];
        float m = -3.4e38f;
#pragma unroll
        for (int t = 0; t < 32; t++) {
            int k = t * 32 + lane;
            e_[t] = (k < vl) ? srow[k] : -1e6f;
            m = fmaxf(m, e_[t]);
        }
#pragma unroll
        for (int o = 16; o > 0; o >>= 1) m = fmaxf(m, __shfl_xor_sync(0xffffffffu, m, o));
        float Z = 0.f;
#pragma unroll
        for (int t = 0; t < 32; t++) {
            e_[t] = ex2a((e_[t] - m) * 1.4426950408889634f);
            Z += e_[t];
        }
#pragma unroll
        for (int o = 16; o > 0; o >>= 1) Z += __shfl_xor_sync(0xffffffffu, Z, o);
        float invZ = 1.0f / Z;
#pragma unroll
        for (int t = 0; t < 32; t++) p_s[w * Kn + t * 32 + lane] = e_[t] * invZ;
    }
    __syncthreads();

    const int qp = (w & 3) * 2;
    const int dq = (w >> 2) * 32;
    const float* vb = v + (size_t)b * Kn * DV + dv0;
    const int n3 = (vl + 15) >> 4;

    float4 vpre[4];
#pragma unroll
    for (int i = 0; i < 4; i++) {
        int e = tid + 256 * i;
        vpre[i] = *(const float4*)&vb[(size_t)(e >> 6) * DV + (e & 63) * 4];
    }

    float4 acc0 = {0,0,0,0};
    float4 acc1 = {0,0,0,0};

    const float* p0 = p_s + qp * Kn;
    const float* p1 = p_s + (qp + 1) * Kn;

    for (int t = 0; t < n3; t++) {
        __syncthreads();
#pragma unroll
        for (int i = 0; i < 4; i++) {
            int e = tid + 256 * i;
            *(float4*)&v_s[(e >> 6) * 256 + (e & 63) * 4] = vpre[i];
        }
        __syncthreads();
        if (t + 1 < n3) {
            int kn = (t + 1) * 16;
#pragma unroll
            for (int i = 0; i < 4; i++) {
                int e = tid + 256 * i;
                vpre[i] = *(const float4*)&vb[(size_t)(kn + (e >> 6)) * DV + (e & 63) * 4];
            }
        }
        int k0 = t * 16;
#pragma unroll
        for (int k4 = 0; k4 < 4; k4++) {
            float4 pa = *(const float4*)&p0[k0 + k4 * 4];
            float4 pb = *(const float4*)&p1[k0 + k4 * 4];
            const float pav[4] = {pa.x, pa.y, pa.z, pa.w};
            const float pbv[4] = {pb.x, pb.y, pb.z, pb.w};
#pragma unroll
            for (int kk = 0; kk < 4; kk++) {
                float4 vv = ((const float4*)&v_s[(k4 * 4 + kk) * 256])[dq + lane];
                acc0.x += pav[kk] * vv.x; acc0.y += pav[kk] * vv.y;
                acc0.z += pav[kk] * vv.z; acc0.w += pav[kk] * vv.w;
                acc1.x += pbv[kk] * vv.x; acc1.y += pbv[kk] * vv.y;
                acc1.z += pbv[kk] * vv.z; acc1.w += pbv[kk] * vv.w;
            }
        }
    }

    {
        float* ob0 = out + (size_t)(b * Qn + q0 + qp) * DV + dv0;
        float* ob1 = out + (size_t)(b * Qn + q0 + qp + 1) * DV + dv0;
        ((float4*)ob0)[dq + lane] = acc0;
        ((float4*)ob1)[dq + lane] = acc1;
    }
}

// ---------------------------------------------------------------------------
extern "C" void kernel_launch(void* const* d_in, const int* in_sizes, int n_in,
                              void* d_out, int out_size) {
    const float* q    = (const float*)d_in[0];
    const float* k    = (const float*)d_in[1];
    const float* v    = (const float*)d_in[2];
    const int*   vlen = (const int*)d_in[3];
    const float* w_q  = (const float*)d_in[4];
    const float* w_k  = (const float*)d_in[5];
    const float* w_v  = (const float*)d_in[6];
    float*       out  = (float*)d_out;

    const int pv_smem = (8192 + 4096) * 4;   // 49152 B
    cudaFuncSetAttribute(pv_kernel, cudaFuncAttributeMaxDynamicSharedMemorySize, pv_smem);

    proj_kernel<<<640, 128>>>(q, w_q, k, w_k);
    proj_reduce_kernel<<<640, 256>>>();
    score_kernel<<<1024, 256>>>(vlen, w_v);
    pv_kernel<<<256, 256, pv_smem>>>(v, vlen, out);
}

// round 7
// speedup vs baseline: 3.1662x; 1.0045x over previous
#include <cuda_runtime.h>

#define B  4
#define Qn 256
#define Kn 1024
#define Dd 512
#define Hh 128
#define DV 512

#define ROWS_ALL (B * Qn + B * Kn)          // 5120 projected rows total

__device__ float g_qh[B * Qn * Hh];         // 512 KB
__device__ float g_kh[B * Kn * Hh];         // 2 MB
__device__ float g_s[B * Qn * Kn];          // 4 MB raw scores
__device__ float g_pp[2][ROWS_ALL * Hh];    // 5 MB proj K-split partials
__device__ float g_po[2][B * Qn * DV];      // 4 MB pv K-split partials

__device__ __forceinline__ float ex2a(float x) {
    float r; asm("ex2.approx.f32 %0, %1;" : "=f"(r) : "f"(x)); return r;
}
__device__ __forceinline__ float tanha(float x) {
    float r; asm("tanh.approx.f32 %0, %1;" : "=f"(r) : "f"(x)); return r;
}

// ---------------------------------------------------------------------------
// Projection GEMM (unchanged from R6): grid 640 x 128, micro 4x4, K-split 2.
// ---------------------------------------------------------------------------
__global__ void proj_kernel(const float* __restrict__ Xq, const float* __restrict__ Wq,
                            const float* __restrict__ Xk, const float* __restrict__ Wk) {
    __shared__ float Xs[32 * 36];
    __shared__ float Ws[32 * 68];

    const int bid = blockIdx.x;
    const int rt  = bid >> 2;
    const int ht  = (bid >> 1) & 1;
    const int ks  = bid & 1;
    const int r0  = rt * 32;
    const int h0  = ht * 64;
    const int d0  = ks * 256;

    const float* Xbase = (r0 < B * Qn) ? (Xq + (size_t)r0 * Dd)
                                       : (Xk + (size_t)(r0 - B * Qn) * Dd);
    const float* W = (r0 < B * Qn) ? Wq : Wk;

    const int tid = threadIdx.x;
    const int tx  = tid & 15;
    const int ty  = tid >> 4;

    float acc[4][4];
#pragma unroll
    for (int r = 0; r < 4; r++)
#pragma unroll
        for (int c = 0; c < 4; c++) acc[r][c] = 0.0f;

    for (int s = 0; s < 8; s++) {
        const int ds = d0 + s * 32;
        __syncthreads();
#pragma unroll
        for (int i = 0; i < 2; i++) {
            int e = tid + 128 * i;
            int r = e >> 3, c4 = (e & 7) * 4;
            float4 xv = *(const float4*)&Xbase[(size_t)r * Dd + ds + c4];
            Xs[(c4 + 0) * 36 + r] = xv.x;
            Xs[(c4 + 1) * 36 + r] = xv.y;
            Xs[(c4 + 2) * 36 + r] = xv.z;
            Xs[(c4 + 3) * 36 + r] = xv.w;
        }
#pragma unroll
        for (int i = 0; i < 4; i++) {
            int e = tid + 128 * i;
            int h = e >> 3, c4 = (e & 7) * 4;
            float4 wv = *(const float4*)&W[(size_t)(h0 + h) * Dd + ds + c4];
            Ws[(c4 + 0) * 68 + h] = wv.x;
            Ws[(c4 + 1) * 68 + h] = wv.y;
            Ws[(c4 + 2) * 68 + h] = wv.z;
            Ws[(c4 + 3) * 68 + h] = wv.w;
        }
        __syncthreads();
#pragma unroll
        for (int dd = 0; dd < 32; dd++) {
            float4 xv = *(const float4*)&Xs[dd * 36 + ty * 4];
            float4 wv = *(const float4*)&Ws[dd * 68 + tx * 4];
            acc[0][0] += xv.x * wv.x; acc[0][1] += xv.x * wv.y;
            acc[0][2] += xv.x * wv.z; acc[0][3] += xv.x * wv.w;
            acc[1][0] += xv.y * wv.x; acc[1][1] += xv.y * wv.y;
            acc[1][2] += xv.y * wv.z; acc[1][3] += xv.y * wv.w;
            acc[2][0] += xv.z * wv.x; acc[2][1] += xv.z * wv.y;
            acc[2][2] += xv.z * wv.z; acc[2][3] += xv.z * wv.w;
            acc[3][0] += xv.w * wv.x; acc[3][1] += xv.w * wv.y;
            acc[3][2] += xv.w * wv.z; acc[3][3] += xv.w * wv.w;
        }
    }

    float* pp = g_pp[ks];
#pragma unroll
    for (int r = 0; r < 4; r++) {
        float4 o = make_float4(acc[r][0], acc[r][1], acc[r][2], acc[r][3]);
        *(float4*)&pp[(size_t)(r0 + ty * 4 + r) * Hh + h0 + tx * 4] = o;
    }
}

__global__ void proj_reduce_kernel() {
    const int i = blockIdx.x * 256 + threadIdx.x;
    const float4 a = ((const float4*)g_pp[0])[i];
    const float4 b = ((const float4*)g_pp[1])[i];
    float4 o = make_float4(a.x + b.x, a.y + b.y, a.z + b.z, a.w + b.w);
    const int qlim = (B * Qn * Hh) / 4;
    if (i < qlim) ((float4*)g_qh)[i] = o;
    else          ((float4*)g_kh)[i - qlim] = o;
}

// ---------------------------------------------------------------------------
// Scores kernel (unchanged). Grid = B*(Q/16)*(K/64) = 1024 CTAs, 256 threads.
// ---------------------------------------------------------------------------
__global__ void score_kernel(const int* __restrict__ vlens,
                             const float* __restrict__ w_v) {
    __shared__ float kh_s[Hh * 65];
    __shared__ float qh_s[16 * Hh];
    __shared__ float wv_s[Hh];

    const int bx = blockIdx.x;
    const int b  = bx >> 8;
    const int qt = (bx >> 4) & 15;
    const int kt = bx & 15;
    const int q0 = qt * 16;
    const int k0 = kt * 64;

    if (k0 >= vlens[b]) return;

    const int tid  = threadIdx.x;
    const int lane = tid & 31;
    const int w    = tid >> 5;

    {
        const float4* src = (const float4*)(g_qh + (size_t)(b * Qn + q0) * Hh);
        ((float4*)qh_s)[tid]       = src[tid];
        ((float4*)qh_s)[tid + 256] = src[tid + 256];
    }
    if (tid < Hh) wv_s[tid] = w_v[tid];

    {
        const float* khg = g_kh + (size_t)(b * Kn + k0) * Hh;
#pragma unroll
        for (int i = 0; i < 8; i++) {
            int e  = tid + 256 * i;
            int kr = e >> 5;
            int h4 = (e & 31) * 4;
            float4 vv = *(const float4*)&khg[(size_t)kr * Hh + h4];
            kh_s[(h4 + 0) * 65 + kr] = vv.x;
            kh_s[(h4 + 1) * 65 + kr] = vv.y;
            kh_s[(h4 + 2) * 65 + kr] = vv.z;
            kh_s[(h4 + 3) * 65 + kr] = vv.w;
        }
    }
    __syncthreads();

    const float* q0p = qh_s + (2 * w) * Hh;
    const float* q1p = qh_s + (2 * w + 1) * Hh;

    float s00 = 0.f, s01 = 0.f, s10 = 0.f, s11 = 0.f;
#pragma unroll 4
    for (int h = 0; h < Hh; h++) {
        float ka = kh_s[h * 65 + lane];
        float kb = kh_s[h * 65 + lane + 32];
        float qa = q0p[h];
        float qb = q1p[h];
        float wvv = wv_s[h];
        s00 += wvv * tanha(qa + ka);
        s01 += wvv * tanha(qa + kb);
        s10 += wvv * tanha(qb + ka);
        s11 += wvv * tanha(qb + kb);
    }

    float* so = g_s + (size_t)(b * Qn + q0 + 2 * w) * Kn + k0;
    so[lane]           = s00;
    so[lane + 32]      = s01;
    so[Kn + lane]      = s10;
    so[Kn + lane + 32] = s11;
}

// ---------------------------------------------------------------------------
// Softmax + partial P@V with parity K-split.
// Grid = B * (Q/8) * 2(dv) * 2(ks) = 512 CTAs, 256 threads (8 warps).
// CTA (b, qg, dvs, ks): 8 q-rows x 256 dv, k-16-tiles t = ks, ks+2, ...
// Softmax recomputed per CTA from raw g_s (read-only; no hazard).
// Writes partial to g_po[ks]; pv_reduce sums the two in fixed order.
// ---------------------------------------------------------------------------
__global__ void pv_kernel(const float* __restrict__ v, const int* __restrict__ vlens,
                          float* __restrict__ unused) {
    extern __shared__ __align__(16) float sm[];
    float* p_s = sm;           // 8192 floats
    float* v_s = sm + 8192;    // 4096 floats (16 k-rows x 256 dv)

    const int bx  = blockIdx.x;
    const int b   =  bx >> 7;
    const int qg  = (bx >> 2) & 31;
    const int dvs = (bx >> 1) & 1;
    const int ks  =  bx & 1;
    const int q0  = qg * 8;
    const int dv0 = dvs * 256;

    const int tid  = threadIdx.x;
    const int lane = tid & 31;
    const int w    = tid >> 5;
    const int vl   = vlens[b];

    // ---- softmax, warp w owns row q0+w (from raw scores) ------------------
    {
        const float* srow = g_s + (size_t)(b * Qn + q0 + w) * Kn;
        float e_[32];
        float m = -3.4e38f;
#pragma unroll
        for (int t = 0; t < 32; t++) {
            int k = t * 32 + lane;
            e_[t] = (k < vl) ? srow[k] : -1e6f;
            m = fmaxf(m, e_[t]);
        }
#pragma unroll
        for (int o = 16; o > 0; o >>= 1) m = fmaxf(m, __shfl_xor_sync(0xffffffffu, m, o));
        float Z = 0.f;
#pragma unroll
        for (int t = 0; t < 32; t++) {
            e_[t] = ex2a((e_[t] - m) * 1.4426950408889634f);
            Z += e_[t];
        }
#pragma unroll
        for (int o = 16; o > 0; o >>= 1) Z += __shfl_xor_sync(0xffffffffu, Z, o);
        float invZ = 1.0f / Z;
#pragma unroll
        for (int t = 0; t < 32; t++) p_s[w * Kn + t * 32 + lane] = e_[t] * invZ;
    }
    __syncthreads();

    // ---- partial P @ V over parity k-tiles ---------------------------------
    const int qp = (w & 3) * 2;
    const int dq = (w >> 2) * 32;
    const float* vb = v + (size_t)b * Kn * DV + dv0;
    const int n3 = (vl + 15) >> 4;          // total 16-k tiles

    float4 vpre[4];
#pragma unroll
    for (int i = 0; i < 4; i++) {           // tile t=ks (k<32, always in-bounds)
        int e = tid + 256 * i;
        vpre[i] = *(const float4*)&vb[(size_t)(ks * 16 + (e >> 6)) * DV + (e & 63) * 4];
    }

    float4 acc0 = {0,0,0,0};
    float4 acc1 = {0,0,0,0};

    const float* p0 = p_s + qp * Kn;
    const float* p1 = p_s + (qp + 1) * Kn;

    for (int t = ks; t < n3; t += 2) {
        __syncthreads();
#pragma unroll
        for (int i = 0; i < 4; i++) {
            int e = tid + 256 * i;
            *(float4*)&v_s[(e >> 6) * 256 + (e & 63) * 4] = vpre[i];
        }
        __syncthreads();
        if (t + 2 < n3) {
            int kn = (t + 2) * 16;
#pragma unroll
            for (int i = 0; i < 4; i++) {
                int e = tid + 256 * i;
                vpre[i] = *(const float4*)&vb[(size_t)(kn + (e >> 6)) * DV + (e & 63) * 4];
            }
        }
        int k0 = t * 16;
#pragma unroll
        for (int k4 = 0; k4 < 4; k4++) {
            float4 pa = *(const float4*)&p0[k0 + k4 * 4];
            float4 pb = *(const float4*)&p1[k0 + k4 * 4];
            const float pav[4] = {pa.x, pa.y, pa.z, pa.w};
            const float pbv[4] = {pb.x, pb.y, pb.z, pb.w};
#pragma unroll
            for (int kk = 0; kk < 4; kk++) {
                float4 vv = ((const float4*)&v_s[(k4 * 4 + kk) * 256])[dq + lane];
                acc0.x += pav[kk] * vv.x; acc0.y += pav[kk] * vv.y;
                acc0.z += pav[kk] * vv.z; acc0.w += pav[kk] * vv.w;
                acc1.x += pbv[kk] * vv.x; acc1.y += pbv[kk] * vv.y;
                acc1.z += pbv[kk] * vv.z; acc1.w += pbv[kk] * vv.w;
            }
        }
    }

    {
        float* po = g_po[ks];
        float* ob0 = po + (size_t)(b * Qn + q0 + qp) * DV + dv0;
        float* ob1 = po + (size_t)(b * Qn + q0 + qp + 1) * DV + dv0;
        ((float4*)ob0)[dq + lane] = acc0;
        ((float4*)ob1)[dq + lane] = acc1;
    }
    (void)unused;
}

// ---------------------------------------------------------------------------
// Sum pv partials into the output. 512 x 256, one float4 per thread.
// ---------------------------------------------------------------------------
__global__ void pv_reduce_kernel(float* __restrict__ out) {
    const int i = blockIdx.x * 256 + threadIdx.x;
    const float4 a = ((const float4*)g_po[0])[i];
    const float4 b = ((const float4*)g_po[1])[i];
    ((float4*)out)[i] = make_float4(a.x + b.x, a.y + b.y, a.z + b.z, a.w + b.w);
}

// ---------------------------------------------------------------------------
extern "C" void kernel_launch(void* const* d_in, const int* in_sizes, int n_in,
                              void* d_out, int out_size) {
    const float* q    = (const float*)d_in[0];
    const float* k    = (const float*)d_in[1];
    const float* v    = (const float*)d_in[2];
    const int*   vlen = (const int*)d_in[3];
    const float* w_q  = (const float*)d_in[4];
    const float* w_k  = (const float*)d_in[5];
    const float* w_v  = (const float*)d_in[6];
    float*       out  = (float*)d_out;

    const int pv_smem = (8192 + 4096) * 4;   // 49152 B
    cudaFuncSetAttribute(pv_kernel, cudaFuncAttributeMaxDynamicSharedMemorySize, pv_smem);

    proj_kernel<<<640, 128>>>(q, w_q, k, w_k);
    proj_reduce_kernel<<<640, 256>>>();
    score_kernel<<<1024, 256>>>(vlen, w_v);
    pv_kernel<<<512, 256, pv_smem>>>(v, vlen, out);
    pv_reduce_kernel<<<512, 256>>>(out);
}